// round 2
// baseline (speedup 1.0000x reference)
#include <cuda_runtime.h>
#include <cstdint>

#define NE 8
#define NT 4096
#define DIN 2048
#define DOUT 2048
#define BM 128
#define BN 64
#define BK 16
#define NTHREADS 256

// ---------------- scratch (device globals: no allocation allowed) ----------------
__device__ int    g_cnt[NE];
__device__ int    g_tok[NE][NT];
__device__ float  g_gw[NE][NT];
__device__ int2   g_re[NT];
__device__ float2 g_rw[NT];

// ---------------- packed f32x2 helpers (Blackwell PTX) ----------------
__device__ __forceinline__ unsigned long long splat2(float x) {
    unsigned long long r;
    asm("mov.b64 %0, {%1, %1};" : "=l"(r) : "f"(x));
    return r;
}
__device__ __forceinline__ void ffma2(unsigned long long& d, unsigned long long a, unsigned long long b) {
    asm("fma.rn.f32x2 %0, %1, %2, %0;" : "+l"(d) : "l"(a), "l"(b));
}
__device__ __forceinline__ float2 unpack2(unsigned long long v) {
    float2 r;
    asm("mov.b64 {%0, %1}, %2;" : "=f"(r.x), "=f"(r.y) : "l"(v));
    return r;
}
// vectorized global reduction (sm_90+): out[0..3] += v
__device__ __forceinline__ void red_add_v4(float* p, float a, float b, float c, float d) {
    asm volatile("red.global.add.v4.f32 [%0], {%1, %2, %3, %4};"
                 :: "l"(p), "f"(a), "f"(b), "f"(c), "f"(d) : "memory");
}

// ---------------- kernel 1: zero expert counters (graph-replay safe) ----------------
__global__ void k_zero() {
    if (threadIdx.x < NE) g_cnt[threadIdx.x] = 0;
}

// ---------------- kernel 2: routing (top-2 of 8, 2-way softmax weight) ----------------
__global__ void k_route(const float* __restrict__ logits) {
    int t = blockIdx.x * blockDim.x + threadIdx.x;
    if (t >= NT) return;
    float l[NE];
#pragma unroll
    for (int e = 0; e < NE; e++) l[e] = logits[t * NE + e];
    int i0 = 0; float v0 = l[0];
#pragma unroll
    for (int e = 1; e < NE; e++) if (l[e] > v0) { v0 = l[e]; i0 = e; }
    int i1 = -1; float v1 = -1e30f;
#pragma unroll
    for (int e = 0; e < NE; e++) if (e != i0 && l[e] > v1) { v1 = l[e]; i1 = e; }
    // renormalized top-2 softmax == softmax over the two winning logits
    float p1  = __expf(v1 - v0);
    float inv = 1.0f / (1.0f + p1);
    float w0 = inv, w1 = p1 * inv;
    int p = atomicAdd(&g_cnt[i0], 1);
    g_tok[i0][p] = t; g_gw[i0][p] = w0;
    p = atomicAdd(&g_cnt[i1], 1);
    g_tok[i1][p] = t; g_gw[i1][p] = w1;
    g_re[t] = make_int2(i0, i1);
    g_rw[t] = make_float2(w0, w1);
}

// ---------------- kernel 3: gate-weighted bias init of d_out ----------------
__global__ void k_bias(const float* __restrict__ b, float* __restrict__ out) {
    int t = blockIdx.x;
    int2   e = g_re[t];
    float2 w = g_rw[t];
    const float4* b0 = (const float4*)(b + (size_t)e.x * DOUT);
    const float4* b1 = (const float4*)(b + (size_t)e.y * DOUT);
    float4* o = (float4*)(out + (size_t)t * DOUT);
    for (int j = threadIdx.x; j < DOUT / 4; j += blockDim.x) {
        float4 x0 = b0[j], x1 = b1[j];
        float4 r;
        r.x = w.x * x0.x + w.y * x1.x;
        r.y = w.x * x0.y + w.y * x1.y;
        r.z = w.x * x0.z + w.y * x1.z;
        r.w = w.x * x0.w + w.y * x1.w;
        o[j] = r;
    }
}

// ---------------- kernel 4: grouped GEMM with gathered A, atomic scatter-add ----------------
// C[t, n] += gw * sum_k x[tok, k] * W[e, n, k]
__global__ __launch_bounds__(NTHREADS, 2)
void k_gemm(const float* __restrict__ x, const float* __restrict__ W,
            float* __restrict__ out) {
    int e   = blockIdx.z;
    int cnt = g_cnt[e];
    int m0  = blockIdx.x * BM;
    if (m0 >= cnt) return;
    int n0  = blockIdx.y * BN;

    __shared__ float As[BK][BM];   // [k][m]
    __shared__ float Bs[BK][BN];   // [k][n]
    __shared__ int   s_tok[BM];
    __shared__ float s_gw[BM];

    int tid = threadIdx.x;
    if (tid < BM) {
        int r = m0 + tid;
        if (r < cnt) { s_tok[tid] = g_tok[e][r]; s_gw[tid] = g_gw[e][r]; }
        else         { s_tok[tid] = g_tok[e][m0]; s_gw[tid] = 0.0f; }
    }
    __syncthreads();

    // A loaders: 2 threads per row (128 rows), each thread 2x float4
    int ar = tid >> 1;
    int ac = (tid & 1) * 8;
    const float* aptr = x + (size_t)s_tok[ar] * DIN + ac;
    // B loaders: 4 threads per row (64 rows), each thread 1x float4
    int br = tid >> 2;
    int bc = (tid & 3) * 4;
    const float* bptr = W + ((size_t)e * DOUT + n0 + br) * DIN + bc;

    int tx = tid & 15;       // n-group: 16 -> 4 cols each
    int ty = tid >> 4;       // m-group: 16 -> 8 rows each
    int mrow = ty * 8;
    int ncol = tx * 4;

    unsigned long long acc[4][4];  // row-pairs x 4 cols, packed f32x2
#pragma unroll
    for (int i = 0; i < 4; i++)
#pragma unroll
        for (int j = 0; j < 4; j++) acc[i][j] = 0ull;

    // prefetch first tile into registers
    float4 a0 = *(const float4*)(aptr);
    float4 a1 = *(const float4*)(aptr + 4);
    float4 bv = *(const float4*)(bptr);

    for (int k0 = 0; k0 < DIN; k0 += BK) {
        // commit staged registers to smem (transposed: [k][m] / [k][n])
        As[ac + 0][ar] = a0.x; As[ac + 1][ar] = a0.y; As[ac + 2][ar] = a0.z; As[ac + 3][ar] = a0.w;
        As[ac + 4][ar] = a1.x; As[ac + 5][ar] = a1.y; As[ac + 6][ar] = a1.z; As[ac + 7][ar] = a1.w;
        Bs[bc + 0][br] = bv.x; Bs[bc + 1][br] = bv.y; Bs[bc + 2][br] = bv.z; Bs[bc + 3][br] = bv.w;
        __syncthreads();

        if (k0 + BK < DIN) {   // prefetch next tile
            a0 = *(const float4*)(aptr + k0 + BK);
            a1 = *(const float4*)(aptr + k0 + BK + 4);
            bv = *(const float4*)(bptr + k0 + BK);
        }

#pragma unroll
        for (int k = 0; k < BK; k++) {
            const unsigned long long* a2 = (const unsigned long long*)&As[k][mrow];
            unsigned long long av0 = a2[0], av1 = a2[1], av2 = a2[2], av3 = a2[3];
            float4 bq = *(const float4*)&Bs[k][ncol];
            unsigned long long b0 = splat2(bq.x), b1 = splat2(bq.y),
                               b2 = splat2(bq.z), b3 = splat2(bq.w);
            ffma2(acc[0][0], av0, b0); ffma2(acc[0][1], av0, b1);
            ffma2(acc[0][2], av0, b2); ffma2(acc[0][3], av0, b3);
            ffma2(acc[1][0], av1, b0); ffma2(acc[1][1], av1, b1);
            ffma2(acc[1][2], av1, b2); ffma2(acc[1][3], av1, b3);
            ffma2(acc[2][0], av2, b0); ffma2(acc[2][1], av2, b1);
            ffma2(acc[2][2], av2, b2); ffma2(acc[2][3], av2, b3);
            ffma2(acc[3][0], av3, b0); ffma2(acc[3][1], av3, b1);
            ffma2(acc[3][2], av3, b2); ffma2(acc[3][3], av3, b3);
        }
        __syncthreads();
    }

    // epilogue: gate-scale and vectorized scatter-add into token rows
#pragma unroll
    for (int i = 0; i < 4; i++) {
        int r0 = mrow + 2 * i;
        int r1 = r0 + 1;
        float2 c0 = unpack2(acc[i][0]);
        float2 c1 = unpack2(acc[i][1]);
        float2 c2 = unpack2(acc[i][2]);
        float2 c3 = unpack2(acc[i][3]);
        if (m0 + r0 < cnt) {
            float w = s_gw[r0];
            float* op = out + (size_t)s_tok[r0] * DOUT + n0 + ncol;
            red_add_v4(op, w * c0.x, w * c1.x, w * c2.x, w * c3.x);
        }
        if (m0 + r1 < cnt) {
            float w = s_gw[r1];
            float* op = out + (size_t)s_tok[r1] * DOUT + n0 + ncol;
            red_add_v4(op, w * c0.y, w * c1.y, w * c2.y, w * c3.y);
        }
    }
}

// ---------------- launch ----------------
extern "C" void kernel_launch(void* const* d_in, const int* in_sizes, int n_in,
                              void* d_out, int out_size) {
    const float* hs     = (const float*)d_in[0];  // [B,S,DIN] -> [NT, DIN]
    const float* logits = (const float*)d_in[1];  // [NT, NE]
    const float* W      = (const float*)d_in[2];  // [NE, DOUT, DIN]
    const float* b      = (const float*)d_in[3];  // [NE, DOUT]
    float* out          = (float*)d_out;          // [NT, DOUT]

    k_zero<<<1, 32>>>();
    k_route<<<NT / 256, 256>>>(logits);
    k_bias<<<NT, 256>>>(b, out);
    dim3 grid(NT / BM, DOUT / BN, NE);  // 32 x 32 x 8; inactive m-tiles exit early
    k_gemm<<<grid, NTHREADS>>>(hs, W, out);
}

// round 5
// speedup vs baseline: 1.8933x; 1.8933x over previous
#include <cuda_runtime.h>
#include <cuda_bf16.h>
#include <cstdint>

#define NE 8
#define NT 4096
#define DIN 2048
#define DOUT 2048
#define SLOTS 9216              // 72 * 128
#define MT_TOT 72               // SLOTS/128
#define K3 6144                 // 3 * DIN (bf16x3 K-concat)
#define KCH 384                 // K3/16 k16-chunks
#define ITERS 192               // KCH/2 (BK=32)
#define NSTAGE 4
#define STAGE_BYTES 16384       // 8KB A + 8KB B
#define DSMEM (NSTAGE * STAGE_BYTES)

// ---------------- device scratch ----------------
__device__ int    g_cnt[NE];
__device__ int    g_base[NE];
__device__ int2   g_re[NT];
__device__ float2 g_rw[NT];
__device__ int2   g_rk[NT];
__device__ int    g_slot_tok[SLOTS];
__device__ float  g_slot_gw[SLOTS];

// fragment-packed images:
// A: [mt(72)][kc(384)][mblk(8)][reg(4)][lane(32)] u32  -> 4096B per (mt,kc)
// B: [e(8)][nt(16)][kc(384)][nblk(16)][reg(2)][lane(32)] u32 -> 4096B per (e,nt,kc)
__device__ uint4 g_A[(size_t)MT_TOT * KCH * 256];
__device__ uint4 g_B[(size_t)NE * 16 * KCH * 256];

// ---------------- helpers ----------------
__device__ __forceinline__ uint32_t smem_u32(const void* p) {
    uint32_t a;
    asm("{ .reg .u64 t; cvta.to.shared.u64 t, %1; cvt.u32.u64 %0, t; }" : "=r"(a) : "l"(p));
    return a;
}
__device__ __forceinline__ void cp16(uint32_t dst, const void* src) {
    asm volatile("cp.async.cg.shared.global [%0], [%1], 16;" :: "r"(dst), "l"(src));
}
__device__ __forceinline__ void red_add_v2(float* p, float a, float b) {
    asm volatile("red.global.add.v2.f32 [%0], {%1, %2};" :: "l"(p), "f"(a), "f"(b) : "memory");
}
__device__ __forceinline__ void mma16816(float* d, const uint32_t* a, const uint32_t* b) {
    asm volatile(
        "mma.sync.aligned.m16n8k16.row.col.f32.bf16.bf16.f32 "
        "{%0,%1,%2,%3}, {%4,%5,%6,%7}, {%8,%9}, {%0,%1,%2,%3};"
        : "+f"(d[0]), "+f"(d[1]), "+f"(d[2]), "+f"(d[3])
        : "r"(a[0]), "r"(a[1]), "r"(a[2]), "r"(a[3]), "r"(b[0]), "r"(b[1]));
}

// ---------------- routing ----------------
__global__ void k_zero() { if (threadIdx.x < NE) g_cnt[threadIdx.x] = 0; }

__global__ void k_route(const float* __restrict__ logits) {
    int t = blockIdx.x * blockDim.x + threadIdx.x;
    if (t >= NT) return;
    float l[NE];
#pragma unroll
    for (int e = 0; e < NE; e++) l[e] = logits[t * NE + e];
    int i0 = 0; float v0 = l[0];
#pragma unroll
    for (int e = 1; e < NE; e++) if (l[e] > v0) { v0 = l[e]; i0 = e; }
    int i1 = -1; float v1 = -1e30f;
#pragma unroll
    for (int e = 0; e < NE; e++) if (e != i0 && l[e] > v1) { v1 = l[e]; i1 = e; }
    float p1  = __expf(v1 - v0);
    float inv = 1.0f / (1.0f + p1);
    int r0 = atomicAdd(&g_cnt[i0], 1);
    int r1 = atomicAdd(&g_cnt[i1], 1);
    g_re[t] = make_int2(i0, i1);
    g_rw[t] = make_float2(inv, p1 * inv);
    g_rk[t] = make_int2(r0, r1);
}

__global__ void k_base() {
    if (threadIdx.x == 0) {
        int acc = 0;
        for (int e = 0; e < NE; e++) { g_base[e] = acc; acc += (g_cnt[e] + 127) & ~127; }
    }
}

__global__ void k_fill() {
    int t = blockIdx.x * blockDim.x + threadIdx.x;
    if (t >= NT) return;
    int2 e = g_re[t]; int2 r = g_rk[t]; float2 w = g_rw[t];
    int s0 = g_base[e.x] + r.x, s1 = g_base[e.y] + r.y;
    g_slot_tok[s0] = t; g_slot_gw[s0] = w.x;
    g_slot_tok[s1] = t; g_slot_gw[s1] = w.y;
}

// ---------------- gate-weighted bias init ----------------
__global__ void k_bias(const float* __restrict__ b, float* __restrict__ out) {
    int t = blockIdx.x;
    int2 e = g_re[t]; float2 w = g_rw[t];
    const float4* b0 = (const float4*)(b + (size_t)e.x * DOUT);
    const float4* b1 = (const float4*)(b + (size_t)e.y * DOUT);
    float4* o = (float4*)(out + (size_t)t * DOUT);
    for (int j = threadIdx.x; j < DOUT / 4; j += blockDim.x) {
        float4 x0 = b0[j], x1 = b1[j];
        o[j] = make_float4(w.x * x0.x + w.y * x1.x, w.x * x0.y + w.y * x1.y,
                           w.x * x0.z + w.y * x1.z, w.x * x0.w + w.y * x1.w);
    }
}

// ---------------- conversion: fp32 -> bf16 hi/lo, fragment-packed ----------------
// pack 8 values (pairs along k) into 4 u32: u[d] = bf16(v[2d]) | bf16(v[2d+1])<<16
__device__ __forceinline__ void split_pack8(const float* v, uint4& hi, uint4& lo) {
    uint32_t h[4], l[4];
#pragma unroll
    for (int d = 0; d < 4; d++) {
        __nv_bfloat16 h0 = __float2bfloat16(v[2 * d]);
        __nv_bfloat16 h1 = __float2bfloat16(v[2 * d + 1]);
        __nv_bfloat16 l0 = __float2bfloat16(v[2 * d]     - __bfloat162float(h0));
        __nv_bfloat16 l1 = __float2bfloat16(v[2 * d + 1] - __bfloat162float(h1));
        h[d] = (uint32_t)__bfloat16_as_ushort(h0) | ((uint32_t)__bfloat16_as_ushort(h1) << 16);
        l[d] = (uint32_t)__bfloat16_as_ushort(l0) | ((uint32_t)__bfloat16_as_ushort(l1) << 16);
    }
    hi = make_uint4(h[0], h[1], h[2], h[3]);
    lo = make_uint4(l[0], l[1], l[2], l[3]);
}

// A image write: mt/blk/row from slot; kp = global k' (mult of 8); L0 = (row%8)*4
__device__ __forceinline__ void wrA(int mt, int blk, int row, int kp, uint4 v) {
    int kc = kp >> 4;
    int reg = ((row >> 3) & 1) + 2 * ((kp >> 3) & 1);
    size_t idx = ((((size_t)mt * KCH + kc) * 8 + blk) * 4 + reg) * 8 + ((row & 7));
    g_A[idx] = v;
}
__global__ void k_convA(const float* __restrict__ x) {
    int s = blockIdx.x;
    int t = g_slot_tok[s];
    int j0 = threadIdx.x * 8;
    float v[8];
    const float4* xp = (const float4*)(x + (size_t)t * DIN + j0);
    float4 a = xp[0], b = xp[1];
    v[0] = a.x; v[1] = a.y; v[2] = a.z; v[3] = a.w;
    v[4] = b.x; v[5] = b.y; v[6] = b.z; v[7] = b.w;
    uint4 hi, lo; split_pack8(v, hi, lo);
    int row = s & 15, blk = (s >> 4) & 7, mt = s >> 7;
    wrA(mt, blk, row, j0,            hi);   // seg0: xh
    wrA(mt, blk, row, j0 + DIN,      hi);   // seg1: xh (pairs with wl)
    wrA(mt, blk, row, j0 + 2 * DIN,  lo);   // seg2: xl (pairs with wh)
}

__device__ __forceinline__ void wrB(int e, int nt, int blk, int nn, int kp, uint4 v) {
    int kc = kp >> 4;
    int reg = (kp >> 3) & 1;
    size_t idx = (((((size_t)e * 16 + nt) * KCH + kc) * 16 + blk) * 2 + reg) * 8 + nn;
    g_B[idx] = v;
}
__global__ void k_convW(const float* __restrict__ W) {
    int bid = blockIdx.x;
    int e = bid >> 11, n = bid & 2047;
    int j0 = threadIdx.x * 8;
    float v[8];
    const float4* wp = (const float4*)(W + ((size_t)e * DOUT + n) * DIN + j0);
    float4 a = wp[0], b = wp[1];
    v[0] = a.x; v[1] = a.y; v[2] = a.z; v[3] = a.w;
    v[4] = b.x; v[5] = b.y; v[6] = b.z; v[7] = b.w;
    uint4 hi, lo; split_pack8(v, hi, lo);
    int nt = n >> 7, blk = (n >> 3) & 15, nn = n & 7;
    wrB(e, nt, blk, nn, j0,           hi);  // seg0: wh
    wrB(e, nt, blk, nn, j0 + DIN,     lo);  // seg1: wl (pairs with xh)
    wrB(e, nt, blk, nn, j0 + 2 * DIN, hi);  // seg2: wh (pairs with xl)
}

// ---------------- grouped GEMM: mma.sync bf16, 4-stage cp.async ----------------
__global__ __launch_bounds__(256, 2)
void k_gemm(float* __restrict__ out) {
    int e = blockIdx.z;
    int cnt = g_cnt[e];
    int m0 = blockIdx.y * 128;
    if (m0 >= cnt) return;
    int nt = blockIdx.x;
    int n0 = nt * 128;
    int gmt = (g_base[e] >> 7) + blockIdx.y;   // global 128-row tile in slot space

    extern __shared__ __align__(16) unsigned char smem[];
    uint32_t sbase = smem_u32(smem);

    __shared__ int   s_tok[128];
    __shared__ float s_gw[128];

    int tid = threadIdx.x, lane = tid & 31, wid = tid >> 5;
    int wm = wid >> 2, wn = wid & 3;          // warp grid 2 x 4, warp tile 64x32

    if (tid < 128) {
        int slot = (gmt << 7) + tid;
        s_tok[tid] = g_slot_tok[slot];
        s_gw[tid]  = (m0 + tid < cnt) ? g_slot_gw[slot] : 0.0f;
    }

    const char* Abase = (const char*)g_A + (size_t)gmt * KCH * 4096;
    const char* Bbase = (const char*)g_B + ((size_t)e * 16 + nt) * KCH * 4096;

    float acc[4][4][4];
#pragma unroll
    for (int i = 0; i < 4; i++)
#pragma unroll
        for (int j = 0; j < 4; j++)
#pragma unroll
            for (int k = 0; k < 4; k++) acc[i][j][k] = 0.0f;

    // stage fill: 8KB A + 8KB B, 256 threads x 32B each half
    auto fill = [&](int st, int it) {
        uint32_t d = sbase + st * STAGE_BYTES + tid * 32;
        const char* sa = Abase + (size_t)it * 8192 + tid * 32;
        cp16(d, sa); cp16(d + 16, sa + 16);
        const char* sb = Bbase + (size_t)it * 8192 + tid * 32;
        cp16(d + 8192, sb); cp16(d + 8192 + 16, sb + 16);
    };

#pragma unroll
    for (int s = 0; s < NSTAGE - 1; s++) {
        fill(s, s);
        asm volatile("cp.async.commit_group;");
    }

    for (int it = 0; it < ITERS; it++) {
        asm volatile("cp.async.wait_group %0;" :: "n"(NSTAGE - 2));
        __syncthreads();

        int st = it & (NSTAGE - 1);
        const uint32_t* sA = (const uint32_t*)(smem + st * STAGE_BYTES);
        const uint32_t* sB = (const uint32_t*)(smem + st * STAGE_BYTES + 8192);
#pragma unroll
        for (int kcs = 0; kcs < 2; kcs++) {
            uint32_t bf[4][2];
#pragma unroll
            for (int nj = 0; nj < 4; nj++)
#pragma unroll
                for (int r = 0; r < 2; r++)
                    bf[nj][r] = sB[(((kcs * 16) + wn * 4 + nj) * 2 + r) * 32 + lane];
            uint32_t af[4][4];
#pragma unroll
            for (int mi = 0; mi < 4; mi++)
#pragma unroll
                for (int r = 0; r < 4; r++)
                    af[mi][r] = sA[(((kcs * 8) + wm * 4 + mi) * 4 + r) * 32 + lane];
#pragma unroll
            for (int mi = 0; mi < 4; mi++)
#pragma unroll
                for (int nj = 0; nj < 4; nj++)
                    mma16816(acc[mi][nj], af[mi], bf[nj]);
        }
        __syncthreads();

        int nx = it + NSTAGE - 1;
        if (nx < ITERS) fill(nx & (NSTAGE - 1), nx);
        asm volatile("cp.async.commit_group;");
    }
    asm volatile("cp.async.wait_group 0;");
    __syncthreads();

    // epilogue: gate-scale + scatter-add (out pre-initialized with gated bias)
#pragma unroll
    for (int mi = 0; mi < 4; mi++) {
        int rbase = wm * 64 + mi * 16 + (lane >> 2);
#pragma unroll
        for (int h = 0; h < 2; h++) {
            int r = rbase + h * 8;
            if (m0 + r < cnt) {
                float w = s_gw[r];
                float* op = out + (size_t)s_tok[r] * DOUT + n0 + wn * 32 + (lane & 3) * 2;
#pragma unroll
                for (int nj = 0; nj < 4; nj++)
                    red_add_v2(op + nj * 8, w * acc[mi][nj][2 * h], w * acc[mi][nj][2 * h + 1]);
            }
        }
    }
}

// ---------------- launch ----------------
extern "C" void kernel_launch(void* const* d_in, const int* in_sizes, int n_in,
                              void* d_out, int out_size) {
    const float* hs     = (const float*)d_in[0];
    const float* logits = (const float*)d_in[1];
    const float* W      = (const float*)d_in[2];
    const float* b      = (const float*)d_in[3];
    float* out          = (float*)d_out;

    cudaFuncSetAttribute(k_gemm, cudaFuncAttributeMaxDynamicSharedMemorySize, DSMEM);

    k_zero<<<1, 32>>>();
    k_route<<<NT / 256, 256>>>(logits);
    k_base<<<1, 32>>>();
    k_fill<<<NT / 256, 256>>>();
    k_bias<<<NT, 256>>>(b, out);
    k_convW<<<NE * DOUT, 256>>>(W);
    k_convA<<<SLOTS, 256>>>(hs);
    dim3 grid(16, 32, NE);   // n-tiles x m-tiles x experts (inactive m-tiles exit)
    k_gemm<<<grid, 256, DSMEM>>>(out);
}